// round 16
// baseline (speedup 1.0000x reference)
#include <cuda_runtime.h>
#include <cuda_fp16.h>
#include <cstdint>

#define BB   4
#define LL   4096
#define DD   256
#define NJT  (LL / 128)

// ---------------------------------------------------------------------------
// Device scratch (allocation-free)
// ---------------------------------------------------------------------------
__device__ __align__(256) __half g_xqh[BB * LL * DD];
__device__ __align__(256) __half g_xql[BB * LL * DD];
__device__ __align__(256) __half g_xkh[BB * LL * DD];
__device__ __align__(256) __half g_xkl[BB * LL * DD];
__device__ __align__(256) __half g_xvh[BB * LL * DD];
__device__ __align__(256) __half g_xvl[BB * LL * DD];
__device__ __align__(256) __half g_wqh[DD * DD];
__device__ __align__(256) __half g_wql[DD * DD];
__device__ __align__(256) __half g_wkh[DD * DD];
__device__ __align__(256) __half g_wkl[DD * DD];
__device__ __align__(256) __half g_wvh[DD * DD];
__device__ __align__(256) __half g_wvl[DD * DD];
__device__ __align__(256) __half g_qhi[BB * LL * DD];
__device__ __align__(256) __half g_khi[BB * LL * DD];
__device__ __align__(256) float  g_vp [BB * LL * DD];
__device__ __align__(256) __half g_Pt [(size_t)BB * LL * LL];
__device__ __align__(256) float  g_ps [(size_t)BB * LL * NJT];
__device__ __align__(256) float  g_f  [BB * LL];
__device__ __align__(256) __half g_vt [BB * DD * LL];

// ---------------------------------------------------------------------------
__device__ __forceinline__ void split_half(float x, __half& h, __half& l) {
    h = __float2half_rn(x);
    l = __float2half_rn(x - __half2float(h));
}

// ---------------------------------------------------------------------------
// Elementwise fp32 -> fp16 hi/lo split, batched over 3 tensors via blockIdx.y
// ---------------------------------------------------------------------------
__global__ void __launch_bounds__(256)
split2x3(const float* __restrict__ x0, __half* __restrict__ h0, __half* __restrict__ l0,
         const float* __restrict__ x1, __half* __restrict__ h1, __half* __restrict__ l1,
         const float* __restrict__ x2, __half* __restrict__ h2, __half* __restrict__ l2,
         int n)
{
    const float* x; __half* h; __half* l;
    if (blockIdx.y == 0)      { x = x0; h = h0; l = l0; }
    else if (blockIdx.y == 1) { x = x1; h = h1; l = l1; }
    else                      { x = x2; h = h2; l = l2; }

    int i = (blockIdx.x * 256 + threadIdx.x) * 4;
    if (i >= n) return;
    float4 v = *(const float4*)(x + i);
    __half a0, b0, a1, b1, a2, b2, a3, b3;
    split_half(v.x, a0, b0);
    split_half(v.y, a1, b1);
    split_half(v.z, a2, b2);
    split_half(v.w, a3, b3);
    __half2 hh01; hh01.x = a0; hh01.y = a1;
    __half2 hh23; hh23.x = a2; hh23.y = a3;
    __half2 ll01; ll01.x = b0; ll01.y = b1;
    __half2 ll23; ll23.x = b2; ll23.y = b3;
    *(__half2*)(h + i)     = hh01;
    *(__half2*)(h + i + 2) = hh23;
    *(__half2*)(l + i)     = ll01;
    *(__half2*)(l + i + 2) = ll23;
}

// ---------------------------------------------------------------------------
// mma.sync + ldmatrix + cp.async primitives
// ---------------------------------------------------------------------------
__device__ __forceinline__ void mma16816(float* d, const uint32_t* a, const uint32_t* b) {
    asm volatile(
        "mma.sync.aligned.m16n8k16.row.col.f32.f16.f16.f32 "
        "{%0,%1,%2,%3}, {%4,%5,%6,%7}, {%8,%9}, {%0,%1,%2,%3};"
        : "+f"(d[0]), "+f"(d[1]), "+f"(d[2]), "+f"(d[3])
        : "r"(a[0]), "r"(a[1]), "r"(a[2]), "r"(a[3]), "r"(b[0]), "r"(b[1]));
}
__device__ __forceinline__ void ldm_x4(uint32_t* r, uint32_t saddr) {
    asm volatile("ldmatrix.sync.aligned.m8n8.x4.shared.b16 {%0,%1,%2,%3}, [%4];"
                 : "=r"(r[0]), "=r"(r[1]), "=r"(r[2]), "=r"(r[3]) : "r"(saddr));
}
__device__ __forceinline__ uint32_t smem_u32p(const void* p) {
    uint32_t a;
    asm("{ .reg .u64 t; cvta.to.shared.u64 t, %1; cvt.u32.u64 %0, t; }"
        : "=r"(a) : "l"(p));
    return a;
}
__device__ __forceinline__ void cp_async16(uint32_t saddr, const void* g) {
    asm volatile("cp.async.cg.shared.global [%0], [%1], 16;"
                 :: "r"(saddr), "l"(g) : "memory");
}
#define CP_COMMIT()  asm volatile("cp.async.commit_group;" ::: "memory")
#define CP_WAIT1()   asm volatile("cp.async.wait_group 1;" ::: "memory")

#define SROW   40
#define PITCH  (SROW * 2)           // 80 B
#define OPSZ   (128 * PITCH)        // 10240 B
#define BUFSZ  (4 * OPSZ)
#define MMA_DYN (2 * BUFSZ)         // 81920 B

// 3-term k16 step (projections only)
#define K16_STEP(ks, aoffh, aoffl, boffh, boffl)                               \
    do {                                                                       \
        uint32_t ah[4][4], al[4][4], bh[4][2], bl[4][2];                       \
        _Pragma("unroll")                                                      \
        for (int mt = 0; mt < 4; mt++) {                                       \
            uint32_t ra = (uint32_t)(wm * 64 + mt * 16 + lar) * PITCH          \
                        + ((ks) + lac) * 2;                                    \
            ldm_x4(ah[mt], (aoffh) + ra);                                      \
            ldm_x4(al[mt], (aoffl) + ra);                                      \
        }                                                                      \
        _Pragma("unroll")                                                      \
        for (int pp = 0; pp < 2; pp++) {                                       \
            uint32_t rb = (uint32_t)(wn * 32 + pp * 16 + lbr) * PITCH          \
                        + ((ks) + lbc) * 2;                                    \
            uint32_t tb[4];                                                    \
            ldm_x4(tb, (boffh) + rb);                                          \
            bh[2 * pp][0] = tb[0]; bh[2 * pp][1] = tb[1];                      \
            bh[2 * pp + 1][0] = tb[2]; bh[2 * pp + 1][1] = tb[3];              \
            ldm_x4(tb, (boffl) + rb);                                          \
            bl[2 * pp][0] = tb[0]; bl[2 * pp][1] = tb[1];                      \
            bl[2 * pp + 1][0] = tb[2]; bl[2 * pp + 1][1] = tb[3];              \
        }                                                                      \
        _Pragma("unroll")                                                      \
        for (int mt = 0; mt < 4; mt++)                                         \
            _Pragma("unroll")                                                  \
            for (int nt = 0; nt < 4; nt++) {                                   \
                mma16816(acc[mt][nt], ah[mt], bh[nt]);                         \
                mma16816(acc[mt][nt], ah[mt], bl[nt]);                         \
                mma16816(acc[mt][nt], al[mt], bh[nt]);                         \
            }                                                                  \
    } while (0)

// 1-term k16 step (score + output GEMMs)
#define K16_STEP1(ks, aoff, boff)                                              \
    do {                                                                       \
        uint32_t ah[4][4], bh[4][2];                                           \
        _Pragma("unroll")                                                      \
        for (int mt = 0; mt < 4; mt++) {                                       \
            uint32_t ra = (uint32_t)(wm * 64 + mt * 16 + lar) * PITCH          \
                        + ((ks) + lac) * 2;                                    \
            ldm_x4(ah[mt], (aoff) + ra);                                       \
        }                                                                      \
        _Pragma("unroll")                                                      \
        for (int pp = 0; pp < 2; pp++) {                                       \
            uint32_t rb = (uint32_t)(wn * 32 + pp * 16 + lbr) * PITCH          \
                        + ((ks) + lbc) * 2;                                    \
            uint32_t tb[4];                                                    \
            ldm_x4(tb, (boff) + rb);                                           \
            bh[2 * pp][0] = tb[0]; bh[2 * pp][1] = tb[1];                      \
            bh[2 * pp + 1][0] = tb[2]; bh[2 * pp + 1][1] = tb[3];              \
        }                                                                      \
        _Pragma("unroll")                                                      \
        for (int mt = 0; mt < 4; mt++)                                         \
            _Pragma("unroll")                                                  \
            for (int nt = 0; nt < 4; nt++)                                     \
                mma16816(acc[mt][nt], ah[mt], bh[nt]);                         \
    } while (0)

// ---------------------------------------------------------------------------
// Projection GEMM on tensor cores (3-term)
// ---------------------------------------------------------------------------
__global__ void __launch_bounds__(256, 2)
proj_mma(const __half* __restrict__ Xh, const __half* __restrict__ Xl,
         const __half* __restrict__ Wh, const __half* __restrict__ Wl,
         const float* __restrict__ bias, float* __restrict__ Cf,
         __half* __restrict__ Oh)
{
    extern __shared__ __align__(16) char dyn[];
    const uint32_t su = smem_u32p(dyn);

    const int t = threadIdx.x;
    const int wid = t >> 5, lane = t & 31;
    const int wm = wid >> 2;
    const int wn = wid & 3;
    const int fr = lane >> 2;
    const int fc = (lane & 3) * 2;
    const int lar = (lane & 7) + ((lane >> 3) & 1) * 8;
    const int lac = (lane >> 4) * 8;
    const int lbr = (lane & 7) + (lane >> 4) * 8;
    const int lbc = ((lane >> 3) & 1) * 8;

    const int m0 = blockIdx.y * 128;
    const int n0 = blockIdx.x * 128;

    float acc[4][4][4];
#pragma unroll
    for (int i = 0; i < 4; i++)
#pragma unroll
        for (int j = 0; j < 4; j++)
#pragma unroll
            for (int e = 0; e < 4; e++) acc[i][j][e] = 0.0f;

    const int srow = t >> 2;
    const int sq   = (t & 3) * 8;

    auto stage = [&](int b, int k0) {
        const uint32_t base = su + b * BUFSZ;
#pragma unroll
        for (int it = 0; it < 2; it++) {
            int row = srow + 64 * it;
            uint32_t so = base + row * PITCH + sq * 2;
            size_t ea = (size_t)(m0 + row) * DD + k0 + sq;
            size_t eb = (size_t)(n0 + row) * DD + k0 + sq;
            cp_async16(so + 0 * OPSZ, Xh + ea);
            cp_async16(so + 1 * OPSZ, Xl + ea);
            cp_async16(so + 2 * OPSZ, Wh + eb);
            cp_async16(so + 3 * OPSZ, Wl + eb);
        }
    };

    const int nchunks = DD >> 5;
    stage(0, 0);
    CP_COMMIT();

    for (int kc = 0; kc < nchunks; kc++) {
        if (kc + 1 < nchunks) stage((kc + 1) & 1, (kc + 1) << 5);
        CP_COMMIT();
        CP_WAIT1();
        __syncthreads();

        const uint32_t bb = su + (kc & 1) * BUFSZ;
        K16_STEP(0,  bb, bb + OPSZ, bb + 2 * OPSZ, bb + 3 * OPSZ);
        K16_STEP(16, bb, bb + OPSZ, bb + 2 * OPSZ, bb + 3 * OPSZ);
        __syncthreads();
    }

#pragma unroll
    for (int mt = 0; mt < 4; mt++) {
#pragma unroll
        for (int h = 0; h < 2; h++) {
            int row = m0 + wm * 64 + mt * 16 + fr + 8 * h;
            size_t rowoff = (size_t)row * DD;
#pragma unroll
            for (int nt = 0; nt < 4; nt++) {
                int col = n0 + wn * 32 + nt * 8 + fc;
                float vx = acc[mt][nt][2 * h]     + bias[col];
                float vy = acc[mt][nt][2 * h + 1] + bias[col + 1];
                if (Oh) {
                    __half2 hh;
                    hh.x = __float2half_rn(vx);
                    hh.y = __float2half_rn(vy);
                    *(__half2*)(Oh + rowoff + col) = hh;
                } else {
                    float2 vv; vv.x = vx; vv.y = vy;
                    *(float2*)(Cf + rowoff + col) = vv;
                }
            }
        }
    }
}

// ---------------------------------------------------------------------------
// Score GEMM (1-term), 64-wide K chunks (4 iterations, half the syncs)
// -> Pt = fp16(exp(s)) transposed [j][i] + per-(i, j-tile) partial sums
// Buffer: [A0, A1, B0, B1] each OPSZ (sub-chunks of 32 cols).
// ---------------------------------------------------------------------------
#define TPP       130
#define SCORE_DYN (2 * 4 * OPSZ)      // 81920

__global__ void __launch_bounds__(256, 2)
score_mma(const __half* __restrict__ Ahg, const __half* __restrict__ Bhg,
          __half* __restrict__ Pt, float* __restrict__ ps, float scale)
{
    extern __shared__ __align__(16) char dyn[];
    const uint32_t su = smem_u32p(dyn);
    __shared__ float redl[128][4];

    const int t = threadIdx.x;
    const int wid = t >> 5, lane = t & 31;
    const int wm = wid >> 2;
    const int wn = wid & 3;
    const int fr = lane >> 2;
    const int fc = (lane & 3) * 2;
    const int lar = (lane & 7) + ((lane >> 3) & 1) * 8;
    const int lac = (lane >> 4) * 8;
    const int lbr = (lane & 7) + (lane >> 4) * 8;
    const int lbc = ((lane >> 3) & 1) * 8;

    const size_t zqk = (size_t)LL * DD;
    Ahg += (size_t)blockIdx.z * zqk;
    Bhg += (size_t)blockIdx.z * zqk;
    Pt  += (size_t)blockIdx.z * LL * LL;
    const int m0 = blockIdx.y * 128;
    const int n0 = blockIdx.x * 128;

    float acc[4][4][4];
#pragma unroll
    for (int i = 0; i < 4; i++)
#pragma unroll
        for (int j = 0; j < 4; j++)
#pragma unroll
            for (int e = 0; e < 4; e++) acc[i][j][e] = 0.0f;

    const int srow = t >> 2;
    const int sq   = (t & 3) * 8;

    auto stage = [&](int b, int k0) {
        const uint32_t base = su + b * (4 * OPSZ);
#pragma unroll
        for (int it = 0; it < 2; it++) {
            int row = srow + 64 * it;
            uint32_t so = base + row * PITCH + sq * 2;
            size_t ea = (size_t)(m0 + row) * DD + k0 + sq;
            size_t eb = (size_t)(n0 + row) * DD + k0 + sq;
            cp_async16(so + 0 * OPSZ, Ahg + ea);
            cp_async16(so + 1 * OPSZ, Ahg + ea + 32);
            cp_async16(so + 2 * OPSZ, Bhg + eb);
            cp_async16(so + 3 * OPSZ, Bhg + eb + 32);
        }
    };

    const int nchunks = DD >> 6;       // 4
    stage(0, 0);
    CP_COMMIT();

    for (int kc = 0; kc < nchunks; kc++) {
        if (kc + 1 < nchunks) stage((kc + 1) & 1, (kc + 1) << 6);
        CP_COMMIT();
        CP_WAIT1();
        __syncthreads();

        const uint32_t bb = su + (kc & 1) * (4 * OPSZ);
        K16_STEP1(0,  bb,        bb + 2 * OPSZ);
        K16_STEP1(16, bb,        bb + 2 * OPSZ);
        K16_STEP1(0,  bb + OPSZ, bb + 3 * OPSZ);
        K16_STEP1(16, bb + OPSZ, bb + 3 * OPSZ);
        __syncthreads();
    }

    // ---- epilogue: exp (no max), sums, in-smem transpose ----
    __half* tp = (__half*)dyn;
#pragma unroll
    for (int mt = 0; mt < 4; mt++)
#pragma unroll
        for (int h = 0; h < 2; h++) {
            int r = wm * 64 + mt * 16 + fr + 8 * h;
            float s = 0.0f;
#pragma unroll
            for (int nt = 0; nt < 4; nt++) {
                float e0 = __expf(acc[mt][nt][2 * h]     * scale);
                float e1 = __expf(acc[mt][nt][2 * h + 1] * scale);
                s += e0 + e1;
                int col = wn * 32 + nt * 8 + fc;
                *(__half2*)&tp[r * TPP + col] =
                    __halves2half2(__float2half_rn(e0), __float2half_rn(e1));
            }
#pragma unroll
            for (int o = 1; o <= 2; o <<= 1)
                s += __shfl_xor_sync(0xffffffffu, s, o);
            if ((lane & 3) == 0) redl[r][wn] = s;
        }
    __syncthreads();
    if (t < 128) {
        float sum = redl[t][0] + redl[t][1] + redl[t][2] + redl[t][3];
        size_t o = ((size_t)blockIdx.z * LL + m0 + t) * NJT + blockIdx.x;
        ps[o] = sum;
    }

    // ---- transposed store: Pt[n0 + j][m0 + i] ----
    const int i2 = t & 63;
    const int jb = t >> 6;
    for (int p = 0; p < 32; p++) {
        int j = jb + p * 4;
        __half a  = tp[(2 * i2)     * TPP + j];
        __half b2 = tp[(2 * i2 + 1) * TPP + j];
        *(__half2*)&Pt[(size_t)(n0 + j) * LL + m0 + 2 * i2] =
            __halves2half2(a, b2);
    }
}

// ---------------------------------------------------------------------------
// Combine: f[row] = 1024 / sum_jt ps[row][jt]
// ---------------------------------------------------------------------------
__global__ void __launch_bounds__(256)
combine(const float* __restrict__ ps, float* __restrict__ f)
{
    const int row = blockIdx.x * 8 + threadIdx.y;
    const int tx  = threadIdx.x;
    float s = ps[(size_t)row * NJT + tx];
#pragma unroll
    for (int o = 16; o > 0; o >>= 1)
        s += __shfl_xor_sync(0xffffffffu, s, o);
    if (tx == 0) f[row] = 1024.0f / s;
}

// ---------------------------------------------------------------------------
// V^T scaled: Vt[b][d][i] = fp16( Vp[b][i][d] * f[b*LL+i] )
// ---------------------------------------------------------------------------
__global__ void __launch_bounds__(256)
v_scale_t(const float* __restrict__ V, const float* __restrict__ f,
          __half* __restrict__ Vt)
{
    const int b = blockIdx.z;
    const float* Vb = V + (size_t)b * LL * DD;
    __shared__ float tile[32][33];
    const int tx = threadIdx.x, ty = threadIdx.y;
    const int d0 = blockIdx.x * 32, i0 = blockIdx.y * 32;

#pragma unroll
    for (int r = 0; r < 4; r++) {
        int i = i0 + ty + r * 8;
        tile[ty + r * 8][tx] = Vb[(size_t)i * DD + d0 + tx];
    }
    __syncthreads();
    const float fi = f[b * LL + i0 + tx];
    const size_t ob = (size_t)b * DD * LL;
#pragma unroll
    for (int r = 0; r < 4; r++) {
        int d = d0 + ty + r * 8;
        Vt[ob + (size_t)d * LL + i0 + tx] =
            __float2half_rn(tile[tx][ty + r * 8] * fi);
    }
}

// ---------------------------------------------------------------------------
// Output GEMM (1-term), 64-wide i chunks (64 iterations, half the syncs):
//   out[b,j,d] = 2^-10 * Pt @ Vt'
// Buffer: [P0, P1, V0, V1] each OPSZ.
// ---------------------------------------------------------------------------
#define AO_DYN (2 * 4 * OPSZ)    // 81920 B

__global__ void __launch_bounds__(256, 2)
attn_out(const __half* __restrict__ Ptg, const __half* __restrict__ Vtg,
         float* __restrict__ out)
{
    extern __shared__ __align__(16) char dyn[];
    const uint32_t su = smem_u32p(dyn);

    const int t = threadIdx.x;
    const int wid = t >> 5, lane = t & 31;
    const int wm = wid >> 2;
    const int wn = wid & 3;
    const int fr = lane >> 2;
    const int fc = (lane & 3) * 2;
    const int lar = (lane & 7) + ((lane >> 3) & 1) * 8;
    const int lac = (lane >> 4) * 8;
    const int lbr = (lane & 7) + (lane >> 4) * 8;
    const int lbc = ((lane >> 3) & 1) * 8;

    const int b = blockIdx.z;
    const __half* Pb = Ptg + (size_t)b * LL * LL;
    const __half* Vb = Vtg + (size_t)b * DD * LL;
    float* Ob = out + (size_t)b * LL * DD;

    const int j0 = blockIdx.y * 128;
    const int d0 = blockIdx.x * 128;

    float acc[4][4][4];
#pragma unroll
    for (int i = 0; i < 4; i++)
#pragma unroll
        for (int j = 0; j < 4; j++)
#pragma unroll
            for (int e = 0; e < 4; e++) acc[i][j][e] = 0.0f;

    const int srow = t >> 2;
    const int sq   = (t & 3) * 8;

    auto stage = [&](int bf, int i0) {
        const uint32_t base = su + bf * (4 * OPSZ);
#pragma unroll
        for (int it = 0; it < 2; it++) {
            int row = srow + 64 * it;
            uint32_t so = base + row * PITCH + sq * 2;
            size_t ep = (size_t)(j0 + row) * LL + i0 + sq;
            size_t ev = (size_t)(d0 + row) * LL + i0 + sq;
            cp_async16(so + 0 * OPSZ, Pb + ep);
            cp_async16(so + 1 * OPSZ, Pb + ep + 32);
            cp_async16(so + 2 * OPSZ, Vb + ev);
            cp_async16(so + 3 * OPSZ, Vb + ev + 32);
        }
    };

    const int nchunks = LL >> 6;   // 64
    stage(0, 0);
    CP_COMMIT();

    for (int kc = 0; kc < nchunks; kc++) {
        if (kc + 1 < nchunks) stage((kc + 1) & 1, (kc + 1) << 6);
        CP_COMMIT();
        CP_WAIT1();
        __syncthreads();

        const uint32_t bb = su + (kc & 1) * (4 * OPSZ);
        K16_STEP1(0,  bb,        bb + 2 * OPSZ);
        K16_STEP1(16, bb,        bb + 2 * OPSZ);
        K16_STEP1(0,  bb + OPSZ, bb + 3 * OPSZ);
        K16_STEP1(16, bb + OPSZ, bb + 3 * OPSZ);
        __syncthreads();
    }

    const float inv = 1.0f / 1024.0f;
#pragma unroll
    for (int mt = 0; mt < 4; mt++) {
        int row = j0 + wm * 64 + mt * 16 + fr;
#pragma unroll
        for (int nt = 0; nt < 4; nt++) {
            int col = d0 + wn * 32 + nt * 8 + fc;
            float2 v0, v1;
            v0.x = acc[mt][nt][0] * inv;
            v0.y = acc[mt][nt][1] * inv;
            v1.x = acc[mt][nt][2] * inv;
            v1.y = acc[mt][nt][3] * inv;
            *(float2*)(Ob + (size_t)row * DD + col)       = v0;
            *(float2*)(Ob + (size_t)(row + 8) * DD + col) = v1;
        }
    }
}

// ---------------------------------------------------------------------------
// Launch
// ---------------------------------------------------------------------------
extern "C" void kernel_launch(void* const* d_in, const int* in_sizes, int n_in,
                              void* d_out, int out_size)
{
    const float* q  = (const float*)d_in[0];
    const float* k  = (const float*)d_in[1];
    const float* v  = (const float*)d_in[2];
    const float* Wq = (const float*)d_in[3];
    const float* bq = (const float*)d_in[4];
    const float* Wk = (const float*)d_in[5];
    const float* bk = (const float*)d_in[6];
    const float* Wv = (const float*)d_in[7];
    const float* bv = (const float*)d_in[8];
    float* out = (float*)d_out;

    __half *xqh, *xql, *xkh, *xkl, *xvh, *xvl;
    __half *wqh, *wql, *wkh, *wkl, *wvh, *wvl;
    __half *qhi, *khi, *vt, *Pt;
    float *vp, *ps, *f;
    cudaGetSymbolAddress((void**)&xqh,  g_xqh);
    cudaGetSymbolAddress((void**)&xql,  g_xql);
    cudaGetSymbolAddress((void**)&xkh,  g_xkh);
    cudaGetSymbolAddress((void**)&xkl,  g_xkl);
    cudaGetSymbolAddress((void**)&xvh,  g_xvh);
    cudaGetSymbolAddress((void**)&xvl,  g_xvl);
    cudaGetSymbolAddress((void**)&wqh,  g_wqh);
    cudaGetSymbolAddress((void**)&wql,  g_wql);
    cudaGetSymbolAddress((void**)&wkh,  g_wkh);
    cudaGetSymbolAddress((void**)&wkl,  g_wkl);
    cudaGetSymbolAddress((void**)&wvh,  g_wvh);
    cudaGetSymbolAddress((void**)&wvl,  g_wvl);
    cudaGetSymbolAddress((void**)&qhi,  g_qhi);
    cudaGetSymbolAddress((void**)&khi,  g_khi);
    cudaGetSymbolAddress((void**)&vp,   g_vp);
    cudaGetSymbolAddress((void**)&Pt,   g_Pt);
    cudaGetSymbolAddress((void**)&ps,   g_ps);
    cudaGetSymbolAddress((void**)&f,    g_f);
    cudaGetSymbolAddress((void**)&vt,   g_vt);

    cudaFuncSetAttribute(proj_mma,
                         cudaFuncAttributeMaxDynamicSharedMemorySize, MMA_DYN);
    cudaFuncSetAttribute(score_mma,
                         cudaFuncAttributeMaxDynamicSharedMemorySize, SCORE_DYN);
    cudaFuncSetAttribute(attn_out,
                         cudaFuncAttributeMaxDynamicSharedMemorySize, AO_DYN);

    const int NX = BB * LL * DD;
    const int NW = DD * DD;

    // 0) Split inputs + weights (batched: 2 launches instead of 6)
    split2x3<<<dim3(NX / 1024, 3), 256>>>(q, xqh, xql, k, xkh, xkl,
                                          v, xvh, xvl, NX);
    split2x3<<<dim3(NW / 1024, 3), 256>>>(Wq, wqh, wql, Wk, wkh, wkl,
                                          Wv, wvh, wvl, NW);

    // 1) Projections (Q,K: fp16 hi; V: fp32)
    dim3 gProj(DD / 128, (BB * LL) / 128, 1);
    proj_mma<<<gProj, 256, MMA_DYN>>>(xqh, xql, wqh, wql, bq, nullptr, qhi);
    proj_mma<<<gProj, 256, MMA_DYN>>>(xkh, xkl, wkh, wkl, bk, nullptr, khi);
    proj_mma<<<gProj, 256, MMA_DYN>>>(xvh, xvl, wvh, wvl, bv, vp, nullptr);

    // 2) Scores (1-term, 64-wide chunks) -> transposed Pt + partial sums
    score_mma<<<dim3(LL / 128, LL / 128, BB), 256, SCORE_DYN>>>(
        qhi, khi, Pt, ps, 0.0625f);

    // 3) Combine -> f = 1024 / rowsum
    combine<<<(BB * LL) / 8, dim3(32, 8)>>>(ps, f);

    // 4) V^T scaled by f
    v_scale_t<<<dim3(DD / 32, LL / 32, BB), dim3(32, 8)>>>(vp, f, vt);

    // 5) Output GEMM (64-wide chunks): out = 2^-10 * Pt @ Vt'
    attn_out<<<dim3(DD / 128, LL / 128, BB), 256, AO_DYN>>>(Pt, vt, out);
}